// round 8
// baseline (speedup 1.0000x reference)
#include <cuda_runtime.h>
#include <cuda_bf16.h>
#include <cstdint>

// ============================================================================
// Problem constants
// ============================================================================
#define B_ROWS 8192

#define MT 128
#define NT 256
#define KC 32                       // k per stage (hi+lo share one 128B row)
#define GEMM_THREADS 256

#define STG_A 0                     // 128 rows x 128B (hi: chunks 0-3, lo: 4-7)
#define STG_W 16384                 // 256 rows x 128B
#define STAGE_BYTES 49152           // 48 KB
#define NSTAGE 4
#define SMEM_TOTAL (NSTAGE * STAGE_BYTES)   // 192 KB

// ============================================================================
// Scratch (__device__ globals; no cudaMalloc allowed)
// ============================================================================
__device__ __nv_bfloat16 g_xHi[B_ROWS * 192];
__device__ __nv_bfloat16 g_xLo[B_ROWS * 192];

__device__ __nv_bfloat16 g_w1Hi[2112 * 192],           g_w1Lo[2112 * 192];
__device__ __nv_bfloat16 g_w2Hi[(size_t)4224 * 2112],  g_w2Lo[(size_t)4224 * 2112];
__device__ __nv_bfloat16 g_w3Hi[(size_t)8448 * 4224],  g_w3Lo[(size_t)8448 * 4224];
__device__ __nv_bfloat16 g_w4Hi[(size_t)4224 * 8448],  g_w4Lo[(size_t)4224 * 8448];
__device__ __nv_bfloat16 g_w5Hi[64 * 4224],            g_w5Lo[64 * 4224];

__device__ __nv_bfloat16 g_actAHi[(size_t)B_ROWS * 8448], g_actALo[(size_t)B_ROWS * 8448];
__device__ __nv_bfloat16 g_actBHi[(size_t)B_ROWS * 4224], g_actBLo[(size_t)B_ROWS * 4224];

// ============================================================================
// PTX helpers
// ============================================================================
__device__ __forceinline__ uint32_t smem_u32(const void* p) {
    uint32_t a;
    asm("{ .reg .u64 t; cvta.to.shared.u64 t, %1; cvt.u32.u64 %0, t; }"
        : "=r"(a) : "l"(p));
    return a;
}

#define CP_ASYNC16(dst, src) \
    asm volatile("cp.async.cg.shared.global [%0], [%1], 16;" :: "r"(dst), "l"(src))

#define CP_COMMIT() asm volatile("cp.async.commit_group;" ::: "memory")
#define CP_WAIT(n)  asm volatile("cp.async.wait_group %0;" :: "n"(n) : "memory")

#define LDSM4(r, addr) \
    asm volatile("ldmatrix.sync.aligned.m8n8.x4.shared.b16 {%0,%1,%2,%3}, [%4];" \
                 : "=r"((r)[0]), "=r"((r)[1]), "=r"((r)[2]), "=r"((r)[3]) : "r"(addr))

#define MMA_BF16(d, a, b0, b1) \
    asm volatile("mma.sync.aligned.m16n8k16.row.col.f32.bf16.bf16.f32 " \
                 "{%0,%1,%2,%3},{%4,%5,%6,%7},{%8,%9},{%0,%1,%2,%3};" \
                 : "+f"((d)[0]), "+f"((d)[1]), "+f"((d)[2]), "+f"((d)[3]) \
                 : "r"((a)[0]), "r"((a)[1]), "r"((a)[2]), "r"((a)[3]), \
                   "r"(b0), "r"(b1))

// swizzled byte offset: row r (128B rows), 16B-chunk c (0..7)
__device__ __forceinline__ uint32_t swz(int r, int c) {
    return (uint32_t)(r * 128 + ((c ^ (r & 7)) << 4));
}

// ============================================================================
// GEMM body: out[8192, Nreal] = act(A @ W^T + bias), bf16x3.
// 4-stage cp.async pipeline, KC=32, hi/lo interleaved per 128B SMEM row.
// NPT: n p-tiles per warp (tile N = NPT*64). OUTFMT 0: bf16 pair, 2: fp32.
// ============================================================================
template<int NPT, int OUTFMT>
__device__ __forceinline__ void gemm_body(
    char* smem,
    const __nv_bfloat16* __restrict__ aHi, const __nv_bfloat16* __restrict__ aLo,
    const __nv_bfloat16* __restrict__ wHi, const __nv_bfloat16* __restrict__ wLo,
    const float* __restrict__ bias,
    __nv_bfloat16* __restrict__ oHi, __nv_bfloat16* __restrict__ oLo,
    float* __restrict__ oF,
    int Nreal, int Kpad, int doRelu)
{
    const uint32_t sb = smem_u32(smem);
    const int tid  = threadIdx.x;
    const int wid  = tid >> 5;
    const int lane = tid & 31;
    const int m0 = blockIdx.y * MT;
    const int n0 = blockIdx.x * NT;
    const int nChunks = Kpad / KC;

    auto load_chunk = [&](int c, int stage) {
        const uint32_t base = sb + stage * STAGE_BYTES;
        const int k0 = c * KC;
        #pragma unroll
        for (int i = 0; i < 2; i++) {                    // A: 128 rows x 4 chunks
            int j = tid + i * GEMM_THREADS;              // 0..511
            int r = j >> 2, cc = j & 3;
            size_t so = (size_t)(m0 + r) * Kpad + k0 + cc * 8;
            CP_ASYNC16(base + STG_A + swz(r, cc),     aHi + so);
            CP_ASYNC16(base + STG_A + swz(r, cc + 4), aLo + so);
        }
        #pragma unroll
        for (int i = 0; i < NPT; i++) {                  // W: NPT*64 rows x 4 chunks
            int j = tid + i * GEMM_THREADS;              // 0..NPT*256-1
            int r = j >> 2, cc = j & 3;
            size_t so = (size_t)(n0 + r) * Kpad + k0 + cc * 8;
            CP_ASYNC16(base + STG_W + swz(r, cc),     wHi + so);
            CP_ASYNC16(base + STG_W + swz(r, cc + 4), wLo + so);
        }
    };

    float acc[4][2 * NPT][4];
    #pragma unroll
    for (int t = 0; t < 4; t++)
        #pragma unroll
        for (int nf = 0; nf < 2 * NPT; nf++)
            #pragma unroll
            for (int e = 0; e < 4; e++) acc[t][nf][e] = 0.0f;

    const int mBase = (wid & 1) * 64;
    const int nBase = (wid >> 1) * (NPT * 16);

    // prologue: fill 3 stages
    #pragma unroll
    for (int c = 0; c < 3; c++) {
        if (c < nChunks) load_chunk(c, c);
        CP_COMMIT();
    }

    for (int i = 0; i < nChunks; i++) {
        CP_WAIT(2);                    // chunk i resident (committed 3 groups ago)
        __syncthreads();               // visible CTA-wide; stage (i+3)%4 consumed

        if (i + 3 < nChunks) load_chunk(i + 3, (i + 3) & 3);
        CP_COMMIT();

        const uint32_t base = sb + (i & 3) * STAGE_BYTES;
        #pragma unroll
        for (int s = 0; s < 2; s++) {                 // 2 x k16 per chunk
            uint32_t aH[4][4], aL[4][4];
            #pragma unroll
            for (int t = 0; t < 4; t++) {
                int row = mBase + t * 16 + (lane & 15);
                int c16 = s * 2 + (lane >> 4);        // 0..3 (hi)
                LDSM4(aH[t], base + STG_A + swz(row, c16));
                LDSM4(aL[t], base + STG_A + swz(row, c16 + 4));
            }
            #pragma unroll
            for (int p = 0; p < NPT; p++) {
                int g = lane >> 3;
                int row = nBase + p * 16 + (lane & 7) + ((g >> 1) << 3);
                int c16 = s * 2 + (g & 1);
                uint32_t bH[4], bL[4];
                LDSM4(bH, base + STG_W + swz(row, c16));
                LDSM4(bL, base + STG_W + swz(row, c16 + 4));
                #pragma unroll
                for (int t = 0; t < 4; t++) {
                    MMA_BF16(acc[t][2 * p],     aH[t], bH[0], bH[1]);
                    MMA_BF16(acc[t][2 * p + 1], aH[t], bH[2], bH[3]);
                }
                #pragma unroll
                for (int t = 0; t < 4; t++) {
                    MMA_BF16(acc[t][2 * p],     aL[t], bH[0], bH[1]);
                    MMA_BF16(acc[t][2 * p + 1], aL[t], bH[2], bH[3]);
                }
                #pragma unroll
                for (int t = 0; t < 4; t++) {
                    MMA_BF16(acc[t][2 * p],     aH[t], bL[0], bL[1]);
                    MMA_BF16(acc[t][2 * p + 1], aH[t], bL[2], bL[3]);
                }
            }
        }
    }

    // ---------------- epilogue ---------------------------------------------
    const int mW = m0 + mBase;
    const int nW = n0 + nBase;
    #pragma unroll
    for (int t = 0; t < 4; t++) {
        #pragma unroll
        for (int nf = 0; nf < 2 * NPT; nf++) {
            int cc = nW + nf * 8 + ((lane & 3) << 1);
            if (cc >= Nreal) continue;
            int r0 = mW + t * 16 + (lane >> 2);
            int r1 = r0 + 8;
            float bv0 = bias[cc], bv1 = bias[cc + 1];
            float v00 = acc[t][nf][0] + bv0;
            float v01 = acc[t][nf][1] + bv1;
            float v10 = acc[t][nf][2] + bv0;
            float v11 = acc[t][nf][3] + bv1;
            if (doRelu) {
                v00 = fmaxf(v00, 0.f); v01 = fmaxf(v01, 0.f);
                v10 = fmaxf(v10, 0.f); v11 = fmaxf(v11, 0.f);
            }
            if constexpr (OUTFMT == 2) {
                *reinterpret_cast<float2*>(oF + (size_t)r0 * Nreal + cc) = make_float2(v00, v01);
                *reinterpret_cast<float2*>(oF + (size_t)r1 * Nreal + cc) = make_float2(v10, v11);
            } else {
                __nv_bfloat16 h00 = __float2bfloat16(v00), h01 = __float2bfloat16(v01);
                __nv_bfloat16 h10 = __float2bfloat16(v10), h11 = __float2bfloat16(v11);
                __nv_bfloat16 l00 = __float2bfloat16(v00 - __bfloat162float(h00));
                __nv_bfloat16 l01 = __float2bfloat16(v01 - __bfloat162float(h01));
                __nv_bfloat16 l10 = __float2bfloat16(v10 - __bfloat162float(h10));
                __nv_bfloat16 l11 = __float2bfloat16(v11 - __bfloat162float(h11));
                *reinterpret_cast<__nv_bfloat162*>(oHi + (size_t)r0 * Nreal + cc) = __nv_bfloat162(h00, h01);
                *reinterpret_cast<__nv_bfloat162*>(oHi + (size_t)r1 * Nreal + cc) = __nv_bfloat162(h10, h11);
                *reinterpret_cast<__nv_bfloat162*>(oLo + (size_t)r0 * Nreal + cc) = __nv_bfloat162(l00, l01);
                *reinterpret_cast<__nv_bfloat162*>(oLo + (size_t)r1 * Nreal + cc) = __nv_bfloat162(l10, l11);
            }
        }
    }
}

template<int OUTFMT>
__global__ void __launch_bounds__(GEMM_THREADS, 1)
gemm_bf16x3(const __nv_bfloat16* __restrict__ aHi, const __nv_bfloat16* __restrict__ aLo,
            const __nv_bfloat16* __restrict__ wHi, const __nv_bfloat16* __restrict__ wLo,
            const float* __restrict__ bias,
            __nv_bfloat16* __restrict__ oHi, __nv_bfloat16* __restrict__ oLo,
            float* __restrict__ oF,
            int Nreal, int Kpad, int doRelu)
{
    extern __shared__ char smem[];
    const int rem = Nreal - blockIdx.x * NT;   // uniform across block
    if (rem >= 256)
        gemm_body<4, OUTFMT>(smem, aHi, aLo, wHi, wLo, bias, oHi, oLo, oF, Nreal, Kpad, doRelu);
    else if (rem >= 128)
        gemm_body<2, OUTFMT>(smem, aHi, aLo, wHi, wLo, bias, oHi, oLo, oF, Nreal, Kpad, doRelu);
    else
        gemm_body<1, OUTFMT>(smem, aHi, aLo, wHi, wLo, bias, oHi, oLo, oF, Nreal, Kpad, doRelu);
}

// ============================================================================
// Prepack kernels
// ============================================================================
#define CONCAT_BLOCKS 6144
#define W1_BLOCKS 1584
__global__ void prep_fused(const float* __restrict__ state,
                           const float* __restrict__ pref,
                           __nv_bfloat16* __restrict__ xHi, __nv_bfloat16* __restrict__ xLo,
                           const float* __restrict__ w1,
                           __nv_bfloat16* __restrict__ w1Hi, __nv_bfloat16* __restrict__ w1Lo)
{
    if (blockIdx.x < CONCAT_BLOCKS) {
        int idx = blockIdx.x * blockDim.x + threadIdx.x;   // < 8192*192
        int b = idx / 192, c = idx - b * 192;
        float v = 0.0f;
        if (c < 128)      v = state[b * 128 + c];
        else if (c < 132) v = pref[b * 4 + (c - 128)];
        __nv_bfloat16 h = __float2bfloat16(v);
        xHi[idx] = h;
        xLo[idx] = __float2bfloat16(v - __bfloat162float(h));
    } else {
        int idx = (blockIdx.x - CONCAT_BLOCKS) * blockDim.x + threadIdx.x;  // < 2112*192
        int n = idx / 192, k = idx - n * 192;
        float v = (k < 132) ? w1[n * 132 + k] : 0.0f;
        __nv_bfloat16 h = __float2bfloat16(v);
        w1Hi[idx] = h;
        w1Lo[idx] = __float2bfloat16(v - __bfloat162float(h));
    }
}

__global__ void pad_rows_bf16pair(const float* __restrict__ W,
                                  __nv_bfloat16* __restrict__ hi,
                                  __nv_bfloat16* __restrict__ lo,
                                  int K)
{
    int n = blockIdx.x;
    const float4* src = reinterpret_cast<const float4*>(W + (size_t)n * K);
    uint2* dhi = reinterpret_cast<uint2*>(hi + (size_t)n * K);
    uint2* dlo = reinterpret_cast<uint2*>(lo + (size_t)n * K);
    int nv = K >> 2;
    for (int i = threadIdx.x; i < nv; i += blockDim.x) {
        float4 v = src[i];
        __nv_bfloat16 h0 = __float2bfloat16(v.x), h1 = __float2bfloat16(v.y);
        __nv_bfloat16 h2 = __float2bfloat16(v.z), h3 = __float2bfloat16(v.w);
        uint2 uh, ul;
        uh.x = (uint32_t)__bfloat16_as_ushort(h0) | ((uint32_t)__bfloat16_as_ushort(h1) << 16);
        uh.y = (uint32_t)__bfloat16_as_ushort(h2) | ((uint32_t)__bfloat16_as_ushort(h3) << 16);
        __nv_bfloat16 l0 = __float2bfloat16(v.x - __bfloat162float(h0));
        __nv_bfloat16 l1 = __float2bfloat16(v.y - __bfloat162float(h1));
        __nv_bfloat16 l2 = __float2bfloat16(v.z - __bfloat162float(h2));
        __nv_bfloat16 l3 = __float2bfloat16(v.w - __bfloat162float(h3));
        ul.x = (uint32_t)__bfloat16_as_ushort(l0) | ((uint32_t)__bfloat16_as_ushort(l1) << 16);
        ul.y = (uint32_t)__bfloat16_as_ushort(l2) | ((uint32_t)__bfloat16_as_ushort(l3) << 16);
        dhi[i] = uh;
        dlo[i] = ul;
    }
}

// ============================================================================
// envelope
// ============================================================================
__global__ void envelope_kernel(const float* __restrict__ q,
                                const float* __restrict__ pref,
                                float* __restrict__ hq)
{
    int b = blockIdx.x * blockDim.x + threadIdx.x;
    if (b >= B_ROWS) return;
    float p0 = pref[b * 4 + 0], p1 = pref[b * 4 + 1];
    float p2 = pref[b * 4 + 2], p3 = pref[b * 4 + 3];
    const float* qb = q + (size_t)b * 64;
    float best = -3.402823466e+38f;
    int ba = 0;
    #pragma unroll
    for (int a = 0; a < 16; a++) {
        float ip = qb[a * 4 + 0] * p0 + qb[a * 4 + 1] * p1
                 + qb[a * 4 + 2] * p2 + qb[a * 4 + 3] * p3;
        if (ip > best) { best = ip; ba = a; }
    }
    hq[b * 4 + 0] = qb[ba * 4 + 0];
    hq[b * 4 + 1] = qb[ba * 4 + 1];
    hq[b * 4 + 2] = qb[ba * 4 + 2];
    hq[b * 4 + 3] = qb[ba * 4 + 3];
}

// ============================================================================
// launch — launch #4 (ncu capture slot) = L2's GEMM
// ============================================================================
static inline void* sym(const void* s) { void* p; cudaGetSymbolAddress(&p, s); return p; }

extern "C" void kernel_launch(void* const* d_in, const int* in_sizes, int n_in,
                              void* d_out, int out_size)
{
    const float* state = (const float*)d_in[0];
    const float* pref  = (const float*)d_in[1];
    const float* w1 = (const float*)d_in[2];  const float* b1 = (const float*)d_in[3];
    const float* w2 = (const float*)d_in[4];  const float* b2 = (const float*)d_in[5];
    const float* w3 = (const float*)d_in[6];  const float* b3 = (const float*)d_in[7];
    const float* w4 = (const float*)d_in[8];  const float* b4 = (const float*)d_in[9];
    const float* wq = (const float*)d_in[10]; const float* bq = (const float*)d_in[11];

    float* out = (float*)d_out;
    float* hq = out;                       // [8192, 4]
    float* q  = out + (size_t)B_ROWS * 4;  // [8192, 64]

    __nv_bfloat16* xHi = (__nv_bfloat16*)sym(g_xHi);
    __nv_bfloat16* xLo = (__nv_bfloat16*)sym(g_xLo);
    __nv_bfloat16* w1Hi = (__nv_bfloat16*)sym(g_w1Hi); __nv_bfloat16* w1Lo = (__nv_bfloat16*)sym(g_w1Lo);
    __nv_bfloat16* w2Hi = (__nv_bfloat16*)sym(g_w2Hi); __nv_bfloat16* w2Lo = (__nv_bfloat16*)sym(g_w2Lo);
    __nv_bfloat16* w3Hi = (__nv_bfloat16*)sym(g_w3Hi); __nv_bfloat16* w3Lo = (__nv_bfloat16*)sym(g_w3Lo);
    __nv_bfloat16* w4Hi = (__nv_bfloat16*)sym(g_w4Hi); __nv_bfloat16* w4Lo = (__nv_bfloat16*)sym(g_w4Lo);
    __nv_bfloat16* w5Hi = (__nv_bfloat16*)sym(g_w5Hi); __nv_bfloat16* w5Lo = (__nv_bfloat16*)sym(g_w5Lo);
    __nv_bfloat16* aHi = (__nv_bfloat16*)sym(g_actAHi); __nv_bfloat16* aLo = (__nv_bfloat16*)sym(g_actALo);
    __nv_bfloat16* bHi = (__nv_bfloat16*)sym(g_actBHi); __nv_bfloat16* bLo = (__nv_bfloat16*)sym(g_actBLo);

    cudaFuncSetAttribute(gemm_bf16x3<0>, cudaFuncAttributeMaxDynamicSharedMemorySize, SMEM_TOTAL);
    cudaFuncSetAttribute(gemm_bf16x3<2>, cudaFuncAttributeMaxDynamicSharedMemorySize, SMEM_TOTAL);

    dim3 blk(GEMM_THREADS);

    // #1 fused concat + w1 prepack
    prep_fused<<<CONCAT_BLOCKS + W1_BLOCKS, 256>>>(state, pref, xHi, xLo, w1, w1Hi, w1Lo);
    // #2 w2 prepack
    pad_rows_bf16pair<<<4224, 256>>>(w2, w2Hi, w2Lo, 2112);
    // #3 L1: [8192,192] x [2112,192] -> actA (2112)
    gemm_bf16x3<0><<<dim3(9, B_ROWS / MT), blk, SMEM_TOTAL>>>(
        xHi, xLo, w1Hi, w1Lo, b1, aHi, aLo, nullptr, 2112, 192, 1);
    // #4 L2: [8192,2112] x [4224,2112] -> actB (4224)   <-- ncu capture slot
    gemm_bf16x3<0><<<dim3(17, B_ROWS / MT), blk, SMEM_TOTAL>>>(
        aHi, aLo, w2Hi, w2Lo, b2, bHi, bLo, nullptr, 4224, 2112, 1);
    // #5 w3 prepack
    pad_rows_bf16pair<<<8448, 256>>>(w3, w3Hi, w3Lo, 4224);
    // #6 L3: [8192,4224] x [8448,4224] -> actA (8448)
    gemm_bf16x3<0><<<dim3(33, B_ROWS / MT), blk, SMEM_TOTAL>>>(
        bHi, bLo, w3Hi, w3Lo, b3, aHi, aLo, nullptr, 8448, 4224, 1);
    // #7 w4 prepack
    pad_rows_bf16pair<<<4224, 256>>>(w4, w4Hi, w4Lo, 8448);
    // #8 L4: [8192,8448] x [4224,8448] -> actB (4224)
    gemm_bf16x3<0><<<dim3(17, B_ROWS / MT), blk, SMEM_TOTAL>>>(
        aHi, aLo, w4Hi, w4Lo, b4, bHi, bLo, nullptr, 4224, 8448, 1);
    // #9 w5 prepack
    pad_rows_bf16pair<<<64, 256>>>(wq, w5Hi, w5Lo, 4224);
    // #10 L5: [8192,4224] x [64,4224] -> q fp32 (64)
    gemm_bf16x3<2><<<dim3(1, B_ROWS / MT), blk, SMEM_TOTAL>>>(
        bHi, bLo, w5Hi, w5Lo, bq, nullptr, nullptr, q, 64, 4224, 0);
    // #11 envelope
    envelope_kernel<<<(B_ROWS + 255) / 256, 256>>>(q, pref, hq);
}

// round 9
// speedup vs baseline: 1.6888x; 1.6888x over previous
#include <cuda_runtime.h>
#include <cuda_bf16.h>
#include <cstdint>

// ============================================================================
// Problem constants
// ============================================================================
#define B_ROWS 8192

#define MT 128
#define NT 256
#define KC 64
#define GEMM_THREADS 256

#define STG_A_HI 0
#define STG_A_LO 16384
#define STG_W_HI 32768
#define STG_W_LO 65536
#define STAGE_BYTES 98304          // 96 KB
#define SMEM_TOTAL (2 * STAGE_BYTES)

// ============================================================================
// Scratch (__device__ globals; no cudaMalloc allowed)
// ============================================================================
__device__ __nv_bfloat16 g_xHi[B_ROWS * 192];
__device__ __nv_bfloat16 g_xLo[B_ROWS * 192];

__device__ __nv_bfloat16 g_w1Hi[2112 * 192],           g_w1Lo[2112 * 192];
__device__ __nv_bfloat16 g_w2Hi[(size_t)4224 * 2112],  g_w2Lo[(size_t)4224 * 2112];
__device__ __nv_bfloat16 g_w3Hi[(size_t)8448 * 4224],  g_w3Lo[(size_t)8448 * 4224];
__device__ __nv_bfloat16 g_w4Hi[(size_t)4224 * 8448],  g_w4Lo[(size_t)4224 * 8448];
__device__ __nv_bfloat16 g_w5Hi[64 * 4224],            g_w5Lo[64 * 4224];

__device__ __nv_bfloat16 g_actAHi[(size_t)B_ROWS * 8448], g_actALo[(size_t)B_ROWS * 8448];
__device__ __nv_bfloat16 g_actBHi[(size_t)B_ROWS * 4224], g_actBLo[(size_t)B_ROWS * 4224];

// L5 split-K partials: 2 x [8192, 64] fp32
__device__ __align__(16) float g_qpart[2 * B_ROWS * 64];

// ============================================================================
// PTX helpers
// ============================================================================
__device__ __forceinline__ uint32_t smem_u32(const void* p) {
    uint32_t a;
    asm("{ .reg .u64 t; cvta.to.shared.u64 t, %1; cvt.u32.u64 %0, t; }"
        : "=r"(a) : "l"(p));
    return a;
}

#define CP_ASYNC16(dst, src) \
    asm volatile("cp.async.cg.shared.global [%0], [%1], 16;" :: "r"(dst), "l"(src))

#define CP_COMMIT() asm volatile("cp.async.commit_group;" ::: "memory")
#define CP_WAIT(n)  asm volatile("cp.async.wait_group %0;" :: "n"(n) : "memory")

#define LDSM4(r, addr) \
    asm volatile("ldmatrix.sync.aligned.m8n8.x4.shared.b16 {%0,%1,%2,%3}, [%4];" \
                 : "=r"((r)[0]), "=r"((r)[1]), "=r"((r)[2]), "=r"((r)[3]) : "r"(addr))

#define MMA_BF16(d, a, b0, b1) \
    asm volatile("mma.sync.aligned.m16n8k16.row.col.f32.bf16.bf16.f32 " \
                 "{%0,%1,%2,%3},{%4,%5,%6,%7},{%8,%9},{%0,%1,%2,%3};" \
                 : "+f"((d)[0]), "+f"((d)[1]), "+f"((d)[2]), "+f"((d)[3]) \
                 : "r"((a)[0]), "r"((a)[1]), "r"((a)[2]), "r"((a)[3]), \
                   "r"(b0), "r"(b1))

__device__ __forceinline__ uint32_t swz(int r, int c) {
    return (uint32_t)(r * 128 + ((c ^ (r & 7)) << 4));
}

// ============================================================================
// GEMM body (R7 structure: 2-stage KC=64 double buffer).
// Split-K support: grid.y = parts * mBlocks; part p computes kLen columns
// starting at p*kLen (pointers pre-offset), output oF offset by p*partStride.
// NPT: n p-tiles per warp. OUTFMT 0: bf16 hi/lo pair, 2: fp32 (bias nullable).
// ============================================================================
template<int NPT, int OUTFMT>
__device__ __forceinline__ void gemm_body(
    char* smem,
    const __nv_bfloat16* __restrict__ aHi, const __nv_bfloat16* __restrict__ aLo,
    const __nv_bfloat16* __restrict__ wHi, const __nv_bfloat16* __restrict__ wLo,
    const float* __restrict__ bias,
    __nv_bfloat16* __restrict__ oHi, __nv_bfloat16* __restrict__ oLo,
    float* __restrict__ oF,
    int Nreal, int Kstride, int doRelu, int mBlocks, int kLen, size_t partStride)
{
    const uint32_t sb = smem_u32(smem);
    const int tid  = threadIdx.x;
    const int wid  = tid >> 5;
    const int lane = tid & 31;
    const int by   = blockIdx.y;
    const int part = by / mBlocks;
    const int m0 = (by - part * mBlocks) * MT;
    const int n0 = blockIdx.x * NT;
    const int kOff = part * kLen;
    aHi += kOff; aLo += kOff; wHi += kOff; wLo += kOff;
    if (OUTFMT == 2) oF += (size_t)part * partStride;
    const int nChunks = kLen / KC;

    auto load_chunk = [&](int c, int stage) {
        const uint32_t base = sb + stage * STAGE_BYTES;
        const int k0 = c * KC;
        #pragma unroll
        for (int i = 0; i < 4; i++) {                    // A: 1024 x 16B
            int j = tid + i * GEMM_THREADS;
            int r = j >> 3, cc = j & 7;
            uint32_t d = base + swz(r, cc);
            size_t so = (size_t)(m0 + r) * Kstride + k0 + cc * 8;
            CP_ASYNC16(d + STG_A_HI, aHi + so);
            CP_ASYNC16(d + STG_A_LO, aLo + so);
        }
        #pragma unroll
        for (int i = 0; i < 2 * NPT; i++) {              // W: NPT*64 rows x 8 x 16B
            int j = tid + i * GEMM_THREADS;
            int r = j >> 3, cc = j & 7;
            uint32_t d = base + swz(r, cc);
            size_t so = (size_t)(n0 + r) * Kstride + k0 + cc * 8;
            CP_ASYNC16(d + STG_W_HI, wHi + so);
            CP_ASYNC16(d + STG_W_LO, wLo + so);
        }
    };

    float acc[4][2 * NPT][4];
    #pragma unroll
    for (int t = 0; t < 4; t++)
        #pragma unroll
        for (int nf = 0; nf < 2 * NPT; nf++)
            #pragma unroll
            for (int e = 0; e < 4; e++) acc[t][nf][e] = 0.0f;

    const int mBase = (wid & 1) * 64;
    const int nBase = (wid >> 1) * (NPT * 16);

    load_chunk(0, 0);
    CP_COMMIT();

    for (int c = 0; c < nChunks; c++) {
        if (c + 1 < nChunks) {
            load_chunk(c + 1, (c + 1) & 1);
            CP_COMMIT();
            CP_WAIT(1);
        } else {
            CP_WAIT(0);
        }
        __syncthreads();

        const uint32_t base = sb + (c & 1) * STAGE_BYTES;
        #pragma unroll
        for (int s = 0; s < 4; s++) {
            uint32_t aH[4][4], aL[4][4];
            #pragma unroll
            for (int t = 0; t < 4; t++) {
                int row = mBase + t * 16 + (lane & 15);
                int c16 = s * 2 + (lane >> 4);
                uint32_t ad = base + swz(row, c16);
                LDSM4(aH[t], ad + STG_A_HI);
                LDSM4(aL[t], ad + STG_A_LO);
            }
            #pragma unroll
            for (int p = 0; p < NPT; p++) {
                int g = lane >> 3;
                int row = nBase + p * 16 + (lane & 7) + ((g >> 1) << 3);
                int c16 = s * 2 + (g & 1);
                uint32_t wd = base + swz(row, c16);
                uint32_t bH[4], bL[4];
                LDSM4(bH, wd + STG_W_HI);
                LDSM4(bL, wd + STG_W_LO);
                #pragma unroll
                for (int t = 0; t < 4; t++) {
                    MMA_BF16(acc[t][2 * p],     aH[t], bH[0], bH[1]);
                    MMA_BF16(acc[t][2 * p + 1], aH[t], bH[2], bH[3]);
                }
                #pragma unroll
                for (int t = 0; t < 4; t++) {
                    MMA_BF16(acc[t][2 * p],     aL[t], bH[0], bH[1]);
                    MMA_BF16(acc[t][2 * p + 1], aL[t], bH[2], bH[3]);
                }
                #pragma unroll
                for (int t = 0; t < 4; t++) {
                    MMA_BF16(acc[t][2 * p],     aH[t], bL[0], bL[1]);
                    MMA_BF16(acc[t][2 * p + 1], aH[t], bL[2], bL[3]);
                }
            }
        }
        __syncthreads();
    }

    // ---------------- epilogue ---------------------------------------------
    const int mW = m0 + mBase;
    const int nW = n0 + nBase;
    #pragma unroll
    for (int t = 0; t < 4; t++) {
        #pragma unroll
        for (int nf = 0; nf < 2 * NPT; nf++) {
            int cc = nW + nf * 8 + ((lane & 3) << 1);
            if (cc >= Nreal) continue;
            int r0 = mW + t * 16 + (lane >> 2);
            int r1 = r0 + 8;
            float bv0 = bias ? bias[cc] : 0.0f;
            float bv1 = bias ? bias[cc + 1] : 0.0f;
            float v00 = acc[t][nf][0] + bv0;
            float v01 = acc[t][nf][1] + bv1;
            float v10 = acc[t][nf][2] + bv0;
            float v11 = acc[t][nf][3] + bv1;
            if (doRelu) {
                v00 = fmaxf(v00, 0.f); v01 = fmaxf(v01, 0.f);
                v10 = fmaxf(v10, 0.f); v11 = fmaxf(v11, 0.f);
            }
            if constexpr (OUTFMT == 2) {
                *reinterpret_cast<float2*>(oF + (size_t)r0 * Nreal + cc) = make_float2(v00, v01);
                *reinterpret_cast<float2*>(oF + (size_t)r1 * Nreal + cc) = make_float2(v10, v11);
            } else {
                __nv_bfloat16 h00 = __float2bfloat16(v00), h01 = __float2bfloat16(v01);
                __nv_bfloat16 h10 = __float2bfloat16(v10), h11 = __float2bfloat16(v11);
                __nv_bfloat16 l00 = __float2bfloat16(v00 - __bfloat162float(h00));
                __nv_bfloat16 l01 = __float2bfloat16(v01 - __bfloat162float(h01));
                __nv_bfloat16 l10 = __float2bfloat16(v10 - __bfloat162float(h10));
                __nv_bfloat16 l11 = __float2bfloat16(v11 - __bfloat162float(h11));
                *reinterpret_cast<__nv_bfloat162*>(oHi + (size_t)r0 * Nreal + cc) = __nv_bfloat162(h00, h01);
                *reinterpret_cast<__nv_bfloat162*>(oHi + (size_t)r1 * Nreal + cc) = __nv_bfloat162(h10, h11);
                *reinterpret_cast<__nv_bfloat162*>(oLo + (size_t)r0 * Nreal + cc) = __nv_bfloat162(l00, l01);
                *reinterpret_cast<__nv_bfloat162*>(oLo + (size_t)r1 * Nreal + cc) = __nv_bfloat162(l10, l11);
            }
        }
    }
}

template<int OUTFMT>
__global__ void __launch_bounds__(GEMM_THREADS, 1)
gemm_bf16x3(const __nv_bfloat16* __restrict__ aHi, const __nv_bfloat16* __restrict__ aLo,
            const __nv_bfloat16* __restrict__ wHi, const __nv_bfloat16* __restrict__ wLo,
            const float* __restrict__ bias,
            __nv_bfloat16* __restrict__ oHi, __nv_bfloat16* __restrict__ oLo,
            float* __restrict__ oF,
            int Nreal, int Kstride, int doRelu, int mBlocks, int kLen, size_t partStride)
{
    extern __shared__ char smem[];
    const int rem = Nreal - blockIdx.x * NT;   // uniform across block
    if (rem >= 256)
        gemm_body<4, OUTFMT>(smem, aHi, aLo, wHi, wLo, bias, oHi, oLo, oF,
                             Nreal, Kstride, doRelu, mBlocks, kLen, partStride);
    else if (rem >= 128)
        gemm_body<2, OUTFMT>(smem, aHi, aLo, wHi, wLo, bias, oHi, oLo, oF,
                             Nreal, Kstride, doRelu, mBlocks, kLen, partStride);
    else
        gemm_body<1, OUTFMT>(smem, aHi, aLo, wHi, wLo, bias, oHi, oLo, oF,
                             Nreal, Kstride, doRelu, mBlocks, kLen, partStride);
}

// ============================================================================
// Prepack kernels
// ============================================================================
#define CONCAT_BLOCKS 6144
#define W1_BLOCKS 1584
__global__ void prep_fused(const float* __restrict__ state,
                           const float* __restrict__ pref,
                           __nv_bfloat16* __restrict__ xHi, __nv_bfloat16* __restrict__ xLo,
                           const float* __restrict__ w1,
                           __nv_bfloat16* __restrict__ w1Hi, __nv_bfloat16* __restrict__ w1Lo)
{
    if (blockIdx.x < CONCAT_BLOCKS) {
        int idx = blockIdx.x * blockDim.x + threadIdx.x;   // < 8192*192
        int b = idx / 192, c = idx - b * 192;
        float v = 0.0f;
        if (c < 128)      v = state[b * 128 + c];
        else if (c < 132) v = pref[b * 4 + (c - 128)];
        __nv_bfloat16 h = __float2bfloat16(v);
        xHi[idx] = h;
        xLo[idx] = __float2bfloat16(v - __bfloat162float(h));
    } else {
        int idx = (blockIdx.x - CONCAT_BLOCKS) * blockDim.x + threadIdx.x;  // < 2112*192
        int n = idx / 192, k = idx - n * 192;
        float v = (k < 132) ? w1[n * 132 + k] : 0.0f;
        __nv_bfloat16 h = __float2bfloat16(v);
        w1Hi[idx] = h;
        w1Lo[idx] = __float2bfloat16(v - __bfloat162float(h));
    }
}

__global__ void pad_rows_bf16pair(const float* __restrict__ W,
                                  __nv_bfloat16* __restrict__ hi,
                                  __nv_bfloat16* __restrict__ lo,
                                  int K)
{
    int n = blockIdx.x;
    const float4* src = reinterpret_cast<const float4*>(W + (size_t)n * K);
    uint2* dhi = reinterpret_cast<uint2*>(hi + (size_t)n * K);
    uint2* dlo = reinterpret_cast<uint2*>(lo + (size_t)n * K);
    int nv = K >> 2;
    for (int i = threadIdx.x; i < nv; i += blockDim.x) {
        float4 v = src[i];
        __nv_bfloat16 h0 = __float2bfloat16(v.x), h1 = __float2bfloat16(v.y);
        __nv_bfloat16 h2 = __float2bfloat16(v.z), h3 = __float2bfloat16(v.w);
        uint2 uh, ul;
        uh.x = (uint32_t)__bfloat16_as_ushort(h0) | ((uint32_t)__bfloat16_as_ushort(h1) << 16);
        uh.y = (uint32_t)__bfloat16_as_ushort(h2) | ((uint32_t)__bfloat16_as_ushort(h3) << 16);
        __nv_bfloat16 l0 = __float2bfloat16(v.x - __bfloat162float(h0));
        __nv_bfloat16 l1 = __float2bfloat16(v.y - __bfloat162float(h1));
        __nv_bfloat16 l2 = __float2bfloat16(v.z - __bfloat162float(h2));
        __nv_bfloat16 l3 = __float2bfloat16(v.w - __bfloat162float(h3));
        ul.x = (uint32_t)__bfloat16_as_ushort(l0) | ((uint32_t)__bfloat16_as_ushort(l1) << 16);
        ul.y = (uint32_t)__bfloat16_as_ushort(l2) | ((uint32_t)__bfloat16_as_ushort(l3) << 16);
        dhi[i] = uh;
        dlo[i] = ul;
    }
}

// ============================================================================
// envelope + L5 split-K combine: q = part0 + part1 + bias; argmax; write q & hq
// ============================================================================
__global__ void envelope_combine_kernel(const float* __restrict__ qp,
                                        const float* __restrict__ bq,
                                        const float* __restrict__ pref,
                                        float* __restrict__ q,
                                        float* __restrict__ hq)
{
    int b = blockIdx.x * blockDim.x + threadIdx.x;
    if (b >= B_ROWS) return;
    const float* p0v = qp + (size_t)b * 64;
    const float* p1v = qp + (size_t)B_ROWS * 64 + (size_t)b * 64;
    float p0 = pref[b * 4 + 0], p1 = pref[b * 4 + 1];
    float p2 = pref[b * 4 + 2], p3 = pref[b * 4 + 3];
    float qv[64];
    #pragma unroll
    for (int j = 0; j < 64; j += 4) {
        float4 a = *reinterpret_cast<const float4*>(p0v + j);
        float4 c = *reinterpret_cast<const float4*>(p1v + j);
        qv[j + 0] = a.x + c.x + bq[j + 0];
        qv[j + 1] = a.y + c.y + bq[j + 1];
        qv[j + 2] = a.z + c.z + bq[j + 2];
        qv[j + 3] = a.w + c.w + bq[j + 3];
    }
    float best = -3.402823466e+38f;
    int ba = 0;
    #pragma unroll
    for (int a = 0; a < 16; a++) {
        float ip = qv[a * 4 + 0] * p0 + qv[a * 4 + 1] * p1
                 + qv[a * 4 + 2] * p2 + qv[a * 4 + 3] * p3;
        if (ip > best) { best = ip; ba = a; }
    }
    float* qrow = q + (size_t)b * 64;
    #pragma unroll
    for (int j = 0; j < 64; j += 4)
        *reinterpret_cast<float4*>(qrow + j) =
            make_float4(qv[j], qv[j + 1], qv[j + 2], qv[j + 3]);
    hq[b * 4 + 0] = qv[ba * 4 + 0];
    hq[b * 4 + 1] = qv[ba * 4 + 1];
    hq[b * 4 + 2] = qv[ba * 4 + 2];
    hq[b * 4 + 3] = qv[ba * 4 + 3];
}

// ============================================================================
// launch — launch #4 (ncu capture slot) = L2's GEMM
// ============================================================================
static inline void* sym(const void* s) { void* p; cudaGetSymbolAddress(&p, s); return p; }

extern "C" void kernel_launch(void* const* d_in, const int* in_sizes, int n_in,
                              void* d_out, int out_size)
{
    const float* state = (const float*)d_in[0];
    const float* pref  = (const float*)d_in[1];
    const float* w1 = (const float*)d_in[2];  const float* b1 = (const float*)d_in[3];
    const float* w2 = (const float*)d_in[4];  const float* b2 = (const float*)d_in[5];
    const float* w3 = (const float*)d_in[6];  const float* b3 = (const float*)d_in[7];
    const float* w4 = (const float*)d_in[8];  const float* b4 = (const float*)d_in[9];
    const float* wq = (const float*)d_in[10]; const float* bq = (const float*)d_in[11];

    float* out = (float*)d_out;
    float* hq = out;                       // [8192, 4]
    float* q  = out + (size_t)B_ROWS * 4;  // [8192, 64]

    __nv_bfloat16* xHi = (__nv_bfloat16*)sym(g_xHi);
    __nv_bfloat16* xLo = (__nv_bfloat16*)sym(g_xLo);
    __nv_bfloat16* w1Hi = (__nv_bfloat16*)sym(g_w1Hi); __nv_bfloat16* w1Lo = (__nv_bfloat16*)sym(g_w1Lo);
    __nv_bfloat16* w2Hi = (__nv_bfloat16*)sym(g_w2Hi); __nv_bfloat16* w2Lo = (__nv_bfloat16*)sym(g_w2Lo);
    __nv_bfloat16* w3Hi = (__nv_bfloat16*)sym(g_w3Hi); __nv_bfloat16* w3Lo = (__nv_bfloat16*)sym(g_w3Lo);
    __nv_bfloat16* w4Hi = (__nv_bfloat16*)sym(g_w4Hi); __nv_bfloat16* w4Lo = (__nv_bfloat16*)sym(g_w4Lo);
    __nv_bfloat16* w5Hi = (__nv_bfloat16*)sym(g_w5Hi); __nv_bfloat16* w5Lo = (__nv_bfloat16*)sym(g_w5Lo);
    __nv_bfloat16* aHi = (__nv_bfloat16*)sym(g_actAHi); __nv_bfloat16* aLo = (__nv_bfloat16*)sym(g_actALo);
    __nv_bfloat16* bHi = (__nv_bfloat16*)sym(g_actBHi); __nv_bfloat16* bLo = (__nv_bfloat16*)sym(g_actBLo);
    float* qp = (float*)sym(g_qpart);

    cudaFuncSetAttribute(gemm_bf16x3<0>, cudaFuncAttributeMaxDynamicSharedMemorySize, SMEM_TOTAL);
    cudaFuncSetAttribute(gemm_bf16x3<2>, cudaFuncAttributeMaxDynamicSharedMemorySize, SMEM_TOTAL);

    dim3 blk(GEMM_THREADS);

    // #1 fused concat + w1 prepack
    prep_fused<<<CONCAT_BLOCKS + W1_BLOCKS, 256>>>(state, pref, xHi, xLo, w1, w1Hi, w1Lo);
    // #2 w2 prepack
    pad_rows_bf16pair<<<4224, 256>>>(w2, w2Hi, w2Lo, 2112);
    // #3 L1: [8192,192] x [2112,192] -> actA (2112)
    gemm_bf16x3<0><<<dim3(9, 64), blk, SMEM_TOTAL>>>(
        xHi, xLo, w1Hi, w1Lo, b1, aHi, aLo, nullptr, 2112, 192, 1, 64, 192, 0);
    // #4 L2: [8192,2112] x [4224,2112] -> actB (4224)   <-- ncu capture slot
    gemm_bf16x3<0><<<dim3(17, 64), blk, SMEM_TOTAL>>>(
        aHi, aLo, w2Hi, w2Lo, b2, bHi, bLo, nullptr, 4224, 2112, 1, 64, 2112, 0);
    // #5 w3 prepack
    pad_rows_bf16pair<<<8448, 256>>>(w3, w3Hi, w3Lo, 4224);
    // #6 L3: [8192,4224] x [8448,4224] -> actA (8448)
    gemm_bf16x3<0><<<dim3(33, 64), blk, SMEM_TOTAL>>>(
        bHi, bLo, w3Hi, w3Lo, b3, aHi, aLo, nullptr, 8448, 4224, 1, 64, 4224, 0);
    // #7 w4 prepack
    pad_rows_bf16pair<<<4224, 256>>>(w4, w4Hi, w4Lo, 8448);
    // #8 L4: [8192,8448] x [4224,8448] -> actB (4224)
    gemm_bf16x3<0><<<dim3(17, 64), blk, SMEM_TOTAL>>>(
        aHi, aLo, w4Hi, w4Lo, b4, bHi, bLo, nullptr, 4224, 8448, 1, 64, 8448, 0);
    // #9 w5 prepack
    pad_rows_bf16pair<<<64, 256>>>(wq, w5Hi, w5Lo, 4224);
    // #10 L5 split-K: [8192,4224] x [64,4224] -> 2 raw partials (no bias)
    gemm_bf16x3<2><<<dim3(1, 128), blk, SMEM_TOTAL>>>(
        bHi, bLo, w5Hi, w5Lo, nullptr, nullptr, nullptr, qp,
        64, 4224, 0, 64, 2112, (size_t)B_ROWS * 64);
    // #11 combine + envelope
    envelope_combine_kernel<<<(B_ROWS + 255) / 256, 256>>>(qp, bq, pref, q, hq);
}